// round 15
// baseline (speedup 1.0000x reference)
#include <cuda_runtime.h>
#include <cuda_fp16.h>
#include <math.h>
#include <stdint.h>

#define B_TOK 8192
#define D_DIM 1024
#define E_NUM 8

// ---------------- scratch (device globals; no allocs allowed) ----------------
__device__ int    g_counts[E_NUM];   // static-zero-init; reset by combine_kernel each call
__device__ int    g_bucket_tok [E_NUM * B_TOK];
__device__ int    g_bucket_slot[E_NUM * B_TOK];
__device__ float  g_gate[B_TOK * 2];
__device__ float  g_partial[(size_t)B_TOK * 2 * D_DIM];       // exp(expert_out) per slot
__device__ __half g_xhi[(size_t)B_TOK * D_DIM];
__device__ __half g_whi[(size_t)E_NUM * D_DIM * D_DIM];       // W^T fp16, [E][N][K]

// ---------------- PTX helpers (sm_80-baseline only) ----------------
__device__ __forceinline__ uint32_t smem_u32(const void* p) {
    uint32_t a;
    asm("{ .reg .u64 t; cvta.to.shared.u64 t, %1; cvt.u32.u64 %0, t; }" : "=r"(a) : "l"(p));
    return a;
}

#define CP16(dst, src) \
    asm volatile("cp.async.cg.shared.global [%0], [%1], 16;" \
        :: "r"(dst), "l"(__cvta_generic_to_global(src)) : "memory")
#define CP_COMMIT() asm volatile("cp.async.commit_group;" ::: "memory")
#define CP_WAIT1()  asm volatile("cp.async.wait_group 1;" ::: "memory")
#define CP_WAIT0()  asm volatile("cp.async.wait_group 0;" ::: "memory")

#define LDSM4(r, addr) \
    asm volatile("ldmatrix.sync.aligned.m8n8.x4.shared.b16 {%0,%1,%2,%3}, [%4];" \
        : "=r"((r)[0]), "=r"((r)[1]), "=r"((r)[2]), "=r"((r)[3]) : "r"(addr))

#define MMA16816(d, a, b0, b1) \
    asm volatile("mma.sync.aligned.m16n8k16.row.col.f32.f16.f16.f32 " \
        "{%0,%1,%2,%3}, {%4,%5,%6,%7}, {%8,%9}, {%0,%1,%2,%3};" \
        : "+f"((d)[0]), "+f"((d)[1]), "+f"((d)[2]), "+f"((d)[3]) \
        : "r"((a)[0]), "r"((a)[1]), "r"((a)[2]), "r"((a)[3]), "r"(b0), "r"(b1))

#define SWZ(row, chunk) ((uint32_t)((row) * 128 + (((chunk) ^ ((row) & 7)) << 4)))

__device__ __forceinline__ float softplus_stable(float z) {
    return fmaxf(z, 0.0f) + log1pf(expf(-fabsf(z)));
}

// ---------------- kernel 1a: gating + x-split (512 blocks, 64KB smem) ----------
#define TOK_PER_WARP 2
#define GATE_BLKS (B_TOK / (8 * TOK_PER_WARP))   // 512
#define SMEM_PREP 65536   // 2 x [8][1024] floats

__global__ __launch_bounds__(256)
void gating_kernel(const float* __restrict__ x,
                   const float* __restrict__ noise,
                   const float* __restrict__ w_gate,
                   const float* __restrict__ w_noise) {
    extern __shared__ float wsm[];
    float* wg_s = wsm;              // [8][1024]
    float* wn_s = wsm + 8192;       // [8][1024]

    __shared__ int cnt_s[E_NUM];
    __shared__ int base_s[E_NUM];
    __shared__ int buf_s[E_NUM][16];   // slot ids (b*2+k); <=16 tokens/block per expert

    const int bx   = blockIdx.x;
    const int tid  = threadIdx.x;
    const int warp = tid >> 5;
    const int lane = tid & 31;
    const int t0 = (bx * 8 + warp) * TOK_PER_WARP;

    // ---- stage w transposed into smem: w_s[j][d] = w[d][j] ----
    const float4* wg4 = (const float4*)w_gate;
    const float4* wn4 = (const float4*)w_noise;
    for (int f = tid; f < 2048; f += 256) {
        float4 g = wg4[f], n = wn4[f];
        int d = f >> 1, h = (f & 1) << 2;
        wg_s[(h + 0) * 1024 + d] = g.x;  wg_s[(h + 1) * 1024 + d] = g.y;
        wg_s[(h + 2) * 1024 + d] = g.z;  wg_s[(h + 3) * 1024 + d] = g.w;
        wn_s[(h + 0) * 1024 + d] = n.x;  wn_s[(h + 1) * 1024 + d] = n.y;
        wn_s[(h + 2) * 1024 + d] = n.z;  wn_s[(h + 3) * 1024 + d] = n.w;
    }
    if (tid < E_NUM) cnt_s[tid] = 0;
    __syncthreads();

    // ---- single pass: convert x -> fp16 AND accumulate per-lane partial logits ----
    float accG[TOK_PER_WARP][8], accN[TOK_PER_WARP][8];
    #pragma unroll
    for (int t = 0; t < TOK_PER_WARP; t++)
        #pragma unroll
        for (int j = 0; j < 8; j++) { accG[t][j] = 0.f; accN[t][j] = 0.f; }

    #pragma unroll 4
    for (int i = 0; i < 16; i++) {
        int d = 2 * lane + 64 * i;
        float2 xv[TOK_PER_WARP];
        #pragma unroll
        for (int t = 0; t < TOK_PER_WARP; t++) {
            xv[t] = *(const float2*)(x + (size_t)(t0 + t) * D_DIM + d);
            ((__half2*)(g_xhi + (size_t)(t0 + t) * D_DIM))[d >> 1] =
                __halves2half2(__float2half_rn(xv[t].x), __float2half_rn(xv[t].y));
        }
        #pragma unroll
        for (int j = 0; j < 8; j++) {
            float2 g2 = *(const float2*)(wg_s + j * 1024 + d);
            float2 n2 = *(const float2*)(wn_s + j * 1024 + d);
            #pragma unroll
            for (int t = 0; t < TOK_PER_WARP; t++) {
                accG[t][j] = fmaf(xv[t].x, g2.x, fmaf(xv[t].y, g2.y, accG[t][j]));
                accN[t][j] = fmaf(xv[t].x, n2.x, fmaf(xv[t].y, n2.y, accN[t][j]));
            }
        }
    }

    // ---- warp reduction (all lanes hold disjoint d-partials) ----
    #pragma unroll
    for (int t = 0; t < TOK_PER_WARP; t++)
        #pragma unroll
        for (int j = 0; j < 8; j++) {
            #pragma unroll
            for (int off = 16; off > 0; off >>= 1) {
                accG[t][j] += __shfl_xor_sync(0xffffffffu, accG[t][j], off);
                accN[t][j] += __shfl_xor_sync(0xffffffffu, accN[t][j], off);
            }
        }

    // ---- routing (lane 0), block-local smem buckets ----
    if (lane == 0) {
        #pragma unroll
        for (int t = 0; t < TOK_PER_WARP; t++) {
            const int b = t0 + t;
            float logits[8];
            #pragma unroll
            for (int j = 0; j < 8; j++) {
                float sd = softplus_stable(accN[t][j]) + 0.01f;
                logits[j] = fmaf(noise[(size_t)b * E_NUM + j], sd, accG[t][j]);
            }
            int i0 = 0; float v0 = logits[0];
            #pragma unroll
            for (int e = 1; e < 8; e++) { if (logits[e] > v0) { v0 = logits[e]; i0 = e; } }
            int i1 = -1; float v1 = -INFINITY;
            #pragma unroll
            for (int e = 0; e < 8; e++) {
                if (e != i0 && logits[e] > v1) { v1 = logits[e]; i1 = e; }
            }
            float ex = expf(v1 - v0);
            float inv = 1.0f / (1.0f + ex);
            g_gate[b * 2 + 0] = inv;
            g_gate[b * 2 + 1] = ex * inv;

            int p0 = atomicAdd(&cnt_s[i0], 1);
            buf_s[i0][p0] = b * 2 + 0;
            int p1 = atomicAdd(&cnt_s[i1], 1);
            buf_s[i1][p1] = b * 2 + 1;
        }
    }
    __syncthreads();

    // ---- flush: one global atomic per expert per block ----
    if (tid < E_NUM) base_s[tid] = atomicAdd(&g_counts[tid], cnt_s[tid]);
    __syncthreads();
    if (tid < E_NUM * 16) {
        int e = tid >> 4, i = tid & 15;
        if (i < cnt_s[e]) {
            int slot = buf_s[e][i];
            int pos = e * B_TOK + base_s[e] + i;
            g_bucket_tok [pos] = slot >> 1;
            g_bucket_slot[pos] = slot;
        }
    }
}

// ---------------- kernel 1b: W transpose/cast (4096 blocks, static smem only) --
__global__ __launch_bounds__(256)
void prep_w_kernel(const float* __restrict__ W) {
    __shared__ float tile[64][33];
    const int t   = blockIdx.x;
    const int e   = t >> 9;            // 512 tiles per expert
    const int rem = t & 511;
    const int k0  = (rem >> 5) << 6;
    const int n0  = (rem & 31) << 5;
    const int tid = threadIdx.x;
    const float* We = W + (size_t)e * D_DIM * D_DIM;

    #pragma unroll
    for (int i = 0; i < 8; i++) {
        int row = i * 8 + (tid >> 5);
        int col = tid & 31;
        tile[row][col] = We[(size_t)(k0 + row) * D_DIM + n0 + col];
    }
    __syncthreads();

    #pragma unroll
    for (int j = 0; j < 4; j++) {
        int n  = j * 8 + (tid >> 5);
        int k2 = tid & 31;
        __half2 h2 = __halves2half2(__float2half_rn(tile[2 * k2][n]),
                                    __float2half_rn(tile[2 * k2 + 1][n]));
        __half2* dst = (__half2*)(g_whi + ((size_t)(e * D_DIM + n0 + n)) * D_DIM + k0);
        dst[k2] = h2;
    }
}

// ---------------- kernel 2: routed 1-pass fp16 GEMM (128x128, 2 CTAs/SM) ------
#define BMh 128
#define BNh 128
#define BKh 64
#define NCHUNK (D_DIM / BKh)           // 16
#define STG 32768                      // A 16K | B 16K
#define OFF_B 16384
#define NSTAGE 3
#define NTHR 256
#define SMEM_GEMM (1024 + NSTAGE * STG)

__device__ __forceinline__ void load_stage(uint32_t sbuf, const int* stok,
                                           const __half* __restrict__ wh,
                                           int kt, int tid) {
    #pragma unroll
    for (int i = 0; i < 4; i++) {              // A: 128 rows x 8 chunks
        int lin = i * NTHR + tid;
        int row = lin >> 3, ch = lin & 7;
        int tok = stok[row];
        const __half* sa = g_xhi + (size_t)tok * D_DIM + kt + ch * 8;
        CP16(sbuf + SWZ(row, ch), sa);
    }
    #pragma unroll
    for (int i = 0; i < 4; i++) {              // B: 128 rows x 8 chunks
        int lin = i * NTHR + tid;
        int row = lin >> 3, ch = lin & 7;
        const __half* sb = wh + (size_t)row * D_DIM + kt + ch * 8;
        CP16(sbuf + OFF_B + SWZ(row, ch), sb);
    }
}

__global__ __launch_bounds__(NTHR, 2)
void expert_hmma_kernel(const float* __restrict__ bias) {
    const int e     = blockIdx.z;
    const int count = g_counts[e];
    const int m0    = blockIdx.y * BMh;
    if (m0 >= count) return;
    const int n0    = blockIdx.x * BNh;

    extern __shared__ char smraw[];
    int* stok  = (int*)smraw;            // [128]
    int* sslot = (int*)(smraw + 512);    // [128]
    const uint32_t sbase = smem_u32(smraw) + 1024;
    uint32_t sbuf3[NSTAGE];
    #pragma unroll
    for (int s = 0; s < NSTAGE; s++) sbuf3[s] = sbase + s * STG;

    const int tid  = threadIdx.x;
    const int wid  = tid >> 5;
    const int lane = tid & 31;
    const int wm   = (wid & 3) * 32;     // 4 warps over 128 m
    const int wn   = (wid >> 2) * 64;    // 2 warps over 128 n

    if (tid < BMh) {
        int m = m0 + tid;
        bool ok = (m < count);
        stok [tid] = ok ? g_bucket_tok [e * B_TOK + m] : 0;
        sslot[tid] = ok ? g_bucket_slot[e * B_TOK + m] : -1;
    }
    __syncthreads();

    const __half* wh = g_whi + ((size_t)e * D_DIM + n0) * D_DIM;

    float acc[2][8][4];
    #pragma unroll
    for (int mt = 0; mt < 2; mt++)
        #pragma unroll
        for (int nt = 0; nt < 8; nt++)
            #pragma unroll
            for (int c = 0; c < 4; c++) acc[mt][nt][c] = 0.0f;

    load_stage(sbuf3[0], stok, wh, 0, tid);
    CP_COMMIT();
    load_stage(sbuf3[1], stok, wh, BKh, tid);
    CP_COMMIT();

    const int lrow = lane & 15;
    const int lsel = lane >> 4;

    int sidx = 0;
    int pidx = 2;
    for (int c = 0; c < NCHUNK; c++) {
        if (c == NCHUNK - 1) { CP_WAIT0(); } else { CP_WAIT1(); }
        __syncthreads();
        if (c + 2 < NCHUNK) {
            load_stage(sbuf3[pidx], stok, wh, (c + 2) * BKh, tid);
            CP_COMMIT();
        }

        const uint32_t sbuf = sbuf3[sidx];
        #pragma unroll
        for (int ks = 0; ks < 4; ks++) {
            const int chunk = ks * 2 + lsel;
            uint32_t ahi[2][4];
            #pragma unroll
            for (int mt = 0; mt < 2; mt++) {
                int r = wm + mt * 16 + lrow;
                LDSM4(ahi[mt], sbuf + SWZ(r, chunk));
            }
            #pragma unroll
            for (int ng = 0; ng < 4; ng++) {
                int r = wn + ng * 16 + lrow;
                uint32_t bhi[4];
                LDSM4(bhi, sbuf + OFF_B + SWZ(r, chunk));
                #pragma unroll
                for (int mt = 0; mt < 2; mt++) {
                    #pragma unroll
                    for (int o = 0; o < 2; o++)
                        MMA16816(acc[mt][ng * 2 + o], ahi[mt], bhi[o], bhi[2 + o]);
                }
            }
        }

        sidx = (sidx + 1 == NSTAGE) ? 0 : sidx + 1;
        pidx = (pidx + 1 == NSTAGE) ? 0 : pidx + 1;
    }

    // epilogue: fused bias + fast exp, scatter to per-slot partials
    #pragma unroll
    for (int mt = 0; mt < 2; mt++) {
        #pragma unroll
        for (int h = 0; h < 2; h++) {
            int m = wm + mt * 16 + (lane >> 2) + h * 8;
            int slot = sslot[m];
            if (slot < 0) continue;
            float* pr = g_partial + ((size_t)slot << 10);
            #pragma unroll
            for (int nt = 0; nt < 8; nt++) {
                int col = n0 + wn + nt * 8 + (lane & 3) * 2;
                float2 bv = *(const float2*)(bias + (size_t)e * D_DIM + col);
                float2 o;
                o.x = __expf(acc[mt][nt][h * 2 + 0] + bv.x);
                o.y = __expf(acc[mt][nt][h * 2 + 1] + bv.y);
                *(float2*)(pr + col) = o;
            }
        }
    }
}

// ---------------- kernel 3: combine (8 elems/thread, fast log) -----------------
__device__ __forceinline__ float safelog(float c) {
    const float EPSF = 2.2204460492503131e-16f;
    return __logf(c == 0.0f ? EPSF : c);
}

__global__ void combine_kernel(float* __restrict__ out) {
    int idx = blockIdx.x * 256 + threadIdx.x;        // over B*D/8
    int b  = idx >> 7;
    int h8 = (idx & 127) << 3;
    float g0 = g_gate[b * 2 + 0];
    float g1 = g_gate[b * 2 + 1];
    const float* p0p = g_partial + ((size_t)(b * 2 + 0) << 10) + h8;
    const float* p1p = g_partial + ((size_t)(b * 2 + 1) << 10) + h8;
    float4 p0a = *(const float4*)(p0p);
    float4 p0b = *(const float4*)(p0p + 4);
    float4 p1a = *(const float4*)(p1p);
    float4 p1b = *(const float4*)(p1p + 4);
    float4 oa, ob;
    oa.x = safelog(fmaf(g0, p0a.x, g1 * p1a.x));
    oa.y = safelog(fmaf(g0, p0a.y, g1 * p1a.y));
    oa.z = safelog(fmaf(g0, p0a.z, g1 * p1a.z));
    oa.w = safelog(fmaf(g0, p0a.w, g1 * p1a.w));
    ob.x = safelog(fmaf(g0, p0b.x, g1 * p1b.x));
    ob.y = safelog(fmaf(g0, p0b.y, g1 * p1b.y));
    ob.z = safelog(fmaf(g0, p0b.z, g1 * p1b.z));
    ob.w = safelog(fmaf(g0, p0b.w, g1 * p1b.w));
    float* op = out + (size_t)b * D_DIM + h8;
    *(float4*)(op)     = oa;
    *(float4*)(op + 4) = ob;

    // reset bucket counts for the next kernel_launch call
    if (blockIdx.x == 0 && threadIdx.x < E_NUM) g_counts[threadIdx.x] = 0;
}

// ---------------- launch ----------------
extern "C" void kernel_launch(void* const* d_in, const int* in_sizes, int n_in,
                              void* d_out, int out_size) {
    const float* x         = (const float*)d_in[0];
    const float* noise     = (const float*)d_in[1];
    const float* w_gate    = (const float*)d_in[2];
    const float* w_noise   = (const float*)d_in[3];
    const float* W_experts = (const float*)d_in[4];
    const float* b_experts = (const float*)d_in[5];
    float* out = (float*)d_out;

    cudaFuncSetAttribute(gating_kernel,
                         cudaFuncAttributeMaxDynamicSharedMemorySize, SMEM_PREP);
    cudaFuncSetAttribute(expert_hmma_kernel,
                         cudaFuncAttributeMaxDynamicSharedMemorySize, SMEM_GEMM);

    gating_kernel<<<GATE_BLKS, 256, SMEM_PREP>>>(x, noise, w_gate, w_noise);
    prep_w_kernel<<<4096, 256>>>(W_experts);

    dim3 ggrid(D_DIM / BNh, B_TOK / BMh, E_NUM);  // (8, 64, 8)
    expert_hmma_kernel<<<ggrid, NTHR, SMEM_GEMM>>>(b_experts);

    combine_kernel<<<(B_TOK * D_DIM / 8) / 256, 256>>>(out);
}

// round 16
// speedup vs baseline: 1.0462x; 1.0462x over previous
#include <cuda_runtime.h>
#include <cuda_fp16.h>
#include <math.h>
#include <stdint.h>

#define B_TOK 8192
#define D_DIM 1024
#define E_NUM 8

// ---------------- scratch (device globals; no allocs allowed) ----------------
__device__ int    g_counts[E_NUM];   // static-zero-init; reset by combine_kernel each call
__device__ int    g_bucket_tok [E_NUM * B_TOK];
__device__ int    g_bucket_slot[E_NUM * B_TOK];
__device__ float  g_gate[B_TOK * 2];
__device__ float  g_partial[(size_t)B_TOK * 2 * D_DIM];       // exp(expert_out) per slot
__device__ __half g_xhi[(size_t)B_TOK * D_DIM];
__device__ __half g_whi[(size_t)E_NUM * D_DIM * D_DIM];       // W^T fp16, [E][N][K]

// ---------------- PTX helpers (sm_80-baseline only) ----------------
__device__ __forceinline__ uint32_t smem_u32(const void* p) {
    uint32_t a;
    asm("{ .reg .u64 t; cvta.to.shared.u64 t, %1; cvt.u32.u64 %0, t; }" : "=r"(a) : "l"(p));
    return a;
}

#define CP16(dst, src) \
    asm volatile("cp.async.cg.shared.global [%0], [%1], 16;" \
        :: "r"(dst), "l"(__cvta_generic_to_global(src)) : "memory")
#define CP_COMMIT() asm volatile("cp.async.commit_group;" ::: "memory")
#define CP_WAIT1()  asm volatile("cp.async.wait_group 1;" ::: "memory")
#define CP_WAIT0()  asm volatile("cp.async.wait_group 0;" ::: "memory")

#define LDSM4(r, addr) \
    asm volatile("ldmatrix.sync.aligned.m8n8.x4.shared.b16 {%0,%1,%2,%3}, [%4];" \
        : "=r"((r)[0]), "=r"((r)[1]), "=r"((r)[2]), "=r"((r)[3]) : "r"(addr))

#define MMA16816(d, a, b0, b1) \
    asm volatile("mma.sync.aligned.m16n8k16.row.col.f32.f16.f16.f32 " \
        "{%0,%1,%2,%3}, {%4,%5,%6,%7}, {%8,%9}, {%0,%1,%2,%3};" \
        : "+f"((d)[0]), "+f"((d)[1]), "+f"((d)[2]), "+f"((d)[3]) \
        : "r"((a)[0]), "r"((a)[1]), "r"((a)[2]), "r"((a)[3]), "r"(b0), "r"(b1))

#define SWZ(row, chunk) ((uint32_t)((row) * 128 + (((chunk) ^ ((row) & 7)) << 4)))

// fast softplus: log(1+exp(z)) = max(z,0) + log1p(exp(-|z|)); MUFU-based.
// __expf rel err ~2^-22 -> logit perturbation ~1e-6, negligible vs 3e-4 budget.
__device__ __forceinline__ float softplus_fast(float z) {
    float t = __expf(-fabsf(z));
    return fmaxf(z, 0.0f) + __logf(1.0f + t);
}

// ---------------- kernel 1: FUSED gating + x-split + W transpose/cast ----------
// gating: 2 tokens/warp, single pass over x, w in smem, block-aggregated routing
#define TOK_PER_WARP 2
#define GATE_BLKS (B_TOK / (8 * TOK_PER_WARP))   // 512

__device__ void gating_block(const float* __restrict__ x,
                             const float* __restrict__ noise,
                             const float* __restrict__ w_gate,
                             const float* __restrict__ w_noise,
                             float* __restrict__ wsm,   // dynamic smem: [2][8][1024]
                             int bx) {
    float* wg_s = wsm;              // [8][1024]
    float* wn_s = wsm + 8192;       // [8][1024]

    __shared__ int cnt_s[E_NUM];
    __shared__ int base_s[E_NUM];
    __shared__ int buf_s[E_NUM][16];   // slot ids (b*2+k); <=16 tokens/block per expert

    const int tid  = threadIdx.x;
    const int warp = tid >> 5;
    const int lane = tid & 31;
    const int t0 = (bx * 8 + warp) * TOK_PER_WARP;

    // ---- stage w transposed into smem: w_s[j][d] = w[d][j] ----
    const float4* wg4 = (const float4*)w_gate;
    const float4* wn4 = (const float4*)w_noise;
    for (int f = tid; f < 2048; f += 256) {
        float4 g = wg4[f], n = wn4[f];
        int d = f >> 1, h = (f & 1) << 2;
        wg_s[(h + 0) * 1024 + d] = g.x;  wg_s[(h + 1) * 1024 + d] = g.y;
        wg_s[(h + 2) * 1024 + d] = g.z;  wg_s[(h + 3) * 1024 + d] = g.w;
        wn_s[(h + 0) * 1024 + d] = n.x;  wn_s[(h + 1) * 1024 + d] = n.y;
        wn_s[(h + 2) * 1024 + d] = n.z;  wn_s[(h + 3) * 1024 + d] = n.w;
    }
    if (tid < E_NUM) cnt_s[tid] = 0;
    __syncthreads();

    // ---- single pass: convert x -> fp16 AND accumulate per-lane partial logits ----
    float accG[TOK_PER_WARP][8], accN[TOK_PER_WARP][8];
    #pragma unroll
    for (int t = 0; t < TOK_PER_WARP; t++)
        #pragma unroll
        for (int j = 0; j < 8; j++) { accG[t][j] = 0.f; accN[t][j] = 0.f; }

    #pragma unroll 4
    for (int i = 0; i < 16; i++) {
        int d = 2 * lane + 64 * i;
        float2 xv[TOK_PER_WARP];
        #pragma unroll
        for (int t = 0; t < TOK_PER_WARP; t++) {
            xv[t] = *(const float2*)(x + (size_t)(t0 + t) * D_DIM + d);
            ((__half2*)(g_xhi + (size_t)(t0 + t) * D_DIM))[d >> 1] =
                __halves2half2(__float2half_rn(xv[t].x), __float2half_rn(xv[t].y));
        }
        #pragma unroll
        for (int j = 0; j < 8; j++) {
            float2 g2 = *(const float2*)(wg_s + j * 1024 + d);
            float2 n2 = *(const float2*)(wn_s + j * 1024 + d);
            #pragma unroll
            for (int t = 0; t < TOK_PER_WARP; t++) {
                accG[t][j] = fmaf(xv[t].x, g2.x, fmaf(xv[t].y, g2.y, accG[t][j]));
                accN[t][j] = fmaf(xv[t].x, n2.x, fmaf(xv[t].y, n2.y, accN[t][j]));
            }
        }
    }

    // ---- warp reduction (all lanes hold disjoint d-partials) ----
    #pragma unroll
    for (int t = 0; t < TOK_PER_WARP; t++)
        #pragma unroll
        for (int j = 0; j < 8; j++) {
            #pragma unroll
            for (int off = 16; off > 0; off >>= 1) {
                accG[t][j] += __shfl_xor_sync(0xffffffffu, accG[t][j], off);
                accN[t][j] += __shfl_xor_sync(0xffffffffu, accN[t][j], off);
            }
        }

    // ---- routing (lane 0), block-local smem buckets ----
    if (lane == 0) {
        #pragma unroll
        for (int t = 0; t < TOK_PER_WARP; t++) {
            const int b = t0 + t;
            float logits[8];
            #pragma unroll
            for (int j = 0; j < 8; j++) {
                float sd = softplus_fast(accN[t][j]) + 0.01f;
                logits[j] = fmaf(noise[(size_t)b * E_NUM + j], sd, accG[t][j]);
            }
            int i0 = 0; float v0 = logits[0];
            #pragma unroll
            for (int e = 1; e < 8; e++) { if (logits[e] > v0) { v0 = logits[e]; i0 = e; } }
            int i1 = -1; float v1 = -INFINITY;
            #pragma unroll
            for (int e = 0; e < 8; e++) {
                if (e != i0 && logits[e] > v1) { v1 = logits[e]; i1 = e; }
            }
            float ex = __expf(v1 - v0);
            float inv = 1.0f / (1.0f + ex);
            g_gate[b * 2 + 0] = inv;
            g_gate[b * 2 + 1] = ex * inv;

            int p0 = atomicAdd(&cnt_s[i0], 1);
            buf_s[i0][p0] = b * 2 + 0;
            int p1 = atomicAdd(&cnt_s[i1], 1);
            buf_s[i1][p1] = b * 2 + 1;
        }
    }
    __syncthreads();

    // ---- flush: one global atomic per expert per block ----
    if (tid < E_NUM) base_s[tid] = atomicAdd(&g_counts[tid], cnt_s[tid]);
    __syncthreads();
    if (tid < E_NUM * 16) {
        int e = tid >> 4, i = tid & 15;
        if (i < cnt_s[e]) {
            int slot = buf_s[e][i];
            int pos = e * B_TOK + base_s[e] + i;
            g_bucket_tok [pos] = slot >> 1;
            g_bucket_slot[pos] = slot;
        }
    }
}

// prep_w: 64k x 32n tiles, half2 output stores
__device__ void prep_w_block(const float* __restrict__ W, int t) {
    __shared__ float tile[64][33];
    const int e   = t >> 9;            // 512 tiles per expert
    const int rem = t & 511;
    const int k0  = (rem >> 5) << 6;
    const int n0  = (rem & 31) << 5;
    const int tid = threadIdx.x;
    const float* We = W + (size_t)e * D_DIM * D_DIM;

    #pragma unroll
    for (int i = 0; i < 8; i++) {
        int row = i * 8 + (tid >> 5);
        int col = tid & 31;
        tile[row][col] = We[(size_t)(k0 + row) * D_DIM + n0 + col];
    }
    __syncthreads();

    #pragma unroll
    for (int j = 0; j < 4; j++) {
        int n  = j * 8 + (tid >> 5);
        int k2 = tid & 31;
        __half2 h2 = __halves2half2(__float2half_rn(tile[2 * k2][n]),
                                    __float2half_rn(tile[2 * k2 + 1][n]));
        __half2* dst = (__half2*)(g_whi + ((size_t)(e * D_DIM + n0 + n)) * D_DIM + k0);
        dst[k2] = h2;
    }
}

__global__ __launch_bounds__(256)
void prep_fused_kernel(const float* __restrict__ x,
                       const float* __restrict__ noise,
                       const float* __restrict__ w_gate,
                       const float* __restrict__ w_noise,
                       const float* __restrict__ W) {
    extern __shared__ float wsm[];
    const int bx = blockIdx.x;
    if (bx < GATE_BLKS) gating_block(x, noise, w_gate, w_noise, wsm, bx);
    else                prep_w_block(W, bx - GATE_BLKS);
}

#define SMEM_PREP 65536   // 2 x [8][1024] floats

// ---------------- kernel 2: routed 1-pass fp16 GEMM (128x128, 2 CTAs/SM) ------
#define BMh 128
#define BNh 128
#define BKh 64
#define NCHUNK (D_DIM / BKh)           // 16
#define STG 32768                      // A 16K | B 16K
#define OFF_B 16384
#define NSTAGE 3
#define NTHR 256
#define SMEM_GEMM (1024 + NSTAGE * STG)

__device__ __forceinline__ void load_stage(uint32_t sbuf, const int* stok,
                                           const __half* __restrict__ wh,
                                           int kt, int tid) {
    #pragma unroll
    for (int i = 0; i < 4; i++) {              // A: 128 rows x 8 chunks
        int lin = i * NTHR + tid;
        int row = lin >> 3, ch = lin & 7;
        int tok = stok[row];
        const __half* sa = g_xhi + (size_t)tok * D_DIM + kt + ch * 8;
        CP16(sbuf + SWZ(row, ch), sa);
    }
    #pragma unroll
    for (int i = 0; i < 4; i++) {              // B: 128 rows x 8 chunks
        int lin = i * NTHR + tid;
        int row = lin >> 3, ch = lin & 7;
        const __half* sb = wh + (size_t)row * D_DIM + kt + ch * 8;
        CP16(sbuf + OFF_B + SWZ(row, ch), sb);
    }
}

__global__ __launch_bounds__(NTHR, 2)
void expert_hmma_kernel(const float* __restrict__ bias) {
    const int e     = blockIdx.z;
    const int count = g_counts[e];
    const int m0    = blockIdx.y * BMh;
    if (m0 >= count) return;
    const int n0    = blockIdx.x * BNh;

    extern __shared__ char smraw[];
    int* stok  = (int*)smraw;            // [128]
    int* sslot = (int*)(smraw + 512);    // [128]
    const uint32_t sbase = smem_u32(smraw) + 1024;
    uint32_t sbuf3[NSTAGE];
    #pragma unroll
    for (int s = 0; s < NSTAGE; s++) sbuf3[s] = sbase + s * STG;

    const int tid  = threadIdx.x;
    const int wid  = tid >> 5;
    const int lane = tid & 31;
    const int wm   = (wid & 3) * 32;     // 4 warps over 128 m
    const int wn   = (wid >> 2) * 64;    // 2 warps over 128 n

    if (tid < BMh) {
        int m = m0 + tid;
        bool ok = (m < count);
        stok [tid] = ok ? g_bucket_tok [e * B_TOK + m] : 0;
        sslot[tid] = ok ? g_bucket_slot[e * B_TOK + m] : -1;
    }
    __syncthreads();

    const __half* wh = g_whi + ((size_t)e * D_DIM + n0) * D_DIM;

    float acc[2][8][4];
    #pragma unroll
    for (int mt = 0; mt < 2; mt++)
        #pragma unroll
        for (int nt = 0; nt < 8; nt++)
            #pragma unroll
            for (int c = 0; c < 4; c++) acc[mt][nt][c] = 0.0f;

    load_stage(sbuf3[0], stok, wh, 0, tid);
    CP_COMMIT();
    load_stage(sbuf3[1], stok, wh, BKh, tid);
    CP_COMMIT();

    const int lrow = lane & 15;
    const int lsel = lane >> 4;

    int sidx = 0;
    int pidx = 2;
    for (int c = 0; c < NCHUNK; c++) {
        if (c == NCHUNK - 1) { CP_WAIT0(); } else { CP_WAIT1(); }
        __syncthreads();
        if (c + 2 < NCHUNK) {
            load_stage(sbuf3[pidx], stok, wh, (c + 2) * BKh, tid);
            CP_COMMIT();
        }

        const uint32_t sbuf = sbuf3[sidx];
        #pragma unroll
        for (int ks = 0; ks < 4; ks++) {
            const int chunk = ks * 2 + lsel;
            uint32_t ahi[2][4];
            #pragma unroll
            for (int mt = 0; mt < 2; mt++) {
                int r = wm + mt * 16 + lrow;
                LDSM4(ahi[mt], sbuf + SWZ(r, chunk));
            }
            #pragma unroll
            for (int ng = 0; ng < 4; ng++) {
                int r = wn + ng * 16 + lrow;
                uint32_t bhi[4];
                LDSM4(bhi, sbuf + OFF_B + SWZ(r, chunk));
                #pragma unroll
                for (int mt = 0; mt < 2; mt++) {
                    #pragma unroll
                    for (int o = 0; o < 2; o++)
                        MMA16816(acc[mt][ng * 2 + o], ahi[mt], bhi[o], bhi[2 + o]);
                }
            }
        }

        sidx = (sidx + 1 == NSTAGE) ? 0 : sidx + 1;
        pidx = (pidx + 1 == NSTAGE) ? 0 : pidx + 1;
    }

    // epilogue: fused bias + fast exp, scatter to per-slot partials
    #pragma unroll
    for (int mt = 0; mt < 2; mt++) {
        #pragma unroll
        for (int h = 0; h < 2; h++) {
            int m = wm + mt * 16 + (lane >> 2) + h * 8;
            int slot = sslot[m];
            if (slot < 0) continue;
            float* pr = g_partial + ((size_t)slot << 10);
            #pragma unroll
            for (int nt = 0; nt < 8; nt++) {
                int col = n0 + wn + nt * 8 + (lane & 3) * 2;
                float2 bv = *(const float2*)(bias + (size_t)e * D_DIM + col);
                float2 o;
                o.x = __expf(acc[mt][nt][h * 2 + 0] + bv.x);
                o.y = __expf(acc[mt][nt][h * 2 + 1] + bv.y);
                *(float2*)(pr + col) = o;
            }
        }
    }
}

// ---------------- kernel 3: combine (8 elems/thread, fast log) -----------------
__device__ __forceinline__ float safelog(float c) {
    const float EPSF = 2.2204460492503131e-16f;
    return __logf(c == 0.0f ? EPSF : c);
}

__global__ void combine_kernel(float* __restrict__ out) {
    int idx = blockIdx.x * 256 + threadIdx.x;        // over B*D/8
    int b  = idx >> 7;
    int h8 = (idx & 127) << 3;
    float g0 = g_gate[b * 2 + 0];
    float g1 = g_gate[b * 2 + 1];
    const float* p0p = g_partial + ((size_t)(b * 2 + 0) << 10) + h8;
    const float* p1p = g_partial + ((size_t)(b * 2 + 1) << 10) + h8;
    float4 p0a = *(const float4*)(p0p);
    float4 p0b = *(const float4*)(p0p + 4);
    float4 p1a = *(const float4*)(p1p);
    float4 p1b = *(const float4*)(p1p + 4);
    float4 oa, ob;
    oa.x = safelog(fmaf(g0, p0a.x, g1 * p1a.x));
    oa.y = safelog(fmaf(g0, p0a.y, g1 * p1a.y));
    oa.z = safelog(fmaf(g0, p0a.z, g1 * p1a.z));
    oa.w = safelog(fmaf(g0, p0a.w, g1 * p1a.w));
    ob.x = safelog(fmaf(g0, p0b.x, g1 * p1b.x));
    ob.y = safelog(fmaf(g0, p0b.y, g1 * p1b.y));
    ob.z = safelog(fmaf(g0, p0b.z, g1 * p1b.z));
    ob.w = safelog(fmaf(g0, p0b.w, g1 * p1b.w));
    float* op = out + (size_t)b * D_DIM + h8;
    *(float4*)(op)     = oa;
    *(float4*)(op + 4) = ob;

    // reset bucket counts for the next kernel_launch call
    if (blockIdx.x == 0 && threadIdx.x < E_NUM) g_counts[threadIdx.x] = 0;
}

// ---------------- launch ----------------
extern "C" void kernel_launch(void* const* d_in, const int* in_sizes, int n_in,
                              void* d_out, int out_size) {
    const float* x         = (const float*)d_in[0];
    const float* noise     = (const float*)d_in[1];
    const float* w_gate    = (const float*)d_in[2];
    const float* w_noise   = (const float*)d_in[3];
    const float* W_experts = (const float*)d_in[4];
    const float* b_experts = (const float*)d_in[5];
    float* out = (float*)d_out;

    cudaFuncSetAttribute(prep_fused_kernel,
                         cudaFuncAttributeMaxDynamicSharedMemorySize, SMEM_PREP);
    cudaFuncSetAttribute(expert_hmma_kernel,
                         cudaFuncAttributeMaxDynamicSharedMemorySize, SMEM_GEMM);

    prep_fused_kernel<<<GATE_BLKS + 4096, 256, SMEM_PREP>>>(x, noise, w_gate, w_noise, W_experts);

    dim3 ggrid(D_DIM / BNh, B_TOK / BMh, E_NUM);  // (8, 64, 8)
    expert_hmma_kernel<<<ggrid, NTHR, SMEM_GEMM>>>(b_experts);

    combine_kernel<<<(B_TOK * D_DIM / 8) / 256, 256>>>(out);
}

// round 17
// speedup vs baseline: 1.0673x; 1.0202x over previous
#include <cuda_runtime.h>
#include <cuda_fp16.h>
#include <math.h>
#include <stdint.h>

#define B_TOK 8192
#define D_DIM 1024
#define E_NUM 8

// ---------------- scratch (device globals; no allocs allowed) ----------------
__device__ int    g_counts[E_NUM];   // static-zero-init; reset by combine_kernel each call
__device__ int    g_bucket_tok [E_NUM * B_TOK];
__device__ int    g_bucket_slot[E_NUM * B_TOK];
__device__ float  g_gate[B_TOK * 2];
__device__ float  g_partial[(size_t)B_TOK * 2 * D_DIM];       // exp(expert_out) per slot
__device__ __half g_xhi[(size_t)B_TOK * D_DIM];
__device__ __half g_whi[(size_t)E_NUM * D_DIM * D_DIM];       // W^T fp16, [E][N][K]

// ---------------- PTX helpers (sm_80-baseline only) ----------------
__device__ __forceinline__ uint32_t smem_u32(const void* p) {
    uint32_t a;
    asm("{ .reg .u64 t; cvta.to.shared.u64 t, %1; cvt.u32.u64 %0, t; }" : "=r"(a) : "l"(p));
    return a;
}

#define CP16(dst, src) \
    asm volatile("cp.async.cg.shared.global [%0], [%1], 16;" \
        :: "r"(dst), "l"(__cvta_generic_to_global(src)) : "memory")
#define CP_COMMIT() asm volatile("cp.async.commit_group;" ::: "memory")
#define CP_WAIT1()  asm volatile("cp.async.wait_group 1;" ::: "memory")
#define CP_WAIT0()  asm volatile("cp.async.wait_group 0;" ::: "memory")

#define LDSM4(r, addr) \
    asm volatile("ldmatrix.sync.aligned.m8n8.x4.shared.b16 {%0,%1,%2,%3}, [%4];" \
        : "=r"((r)[0]), "=r"((r)[1]), "=r"((r)[2]), "=r"((r)[3]) : "r"(addr))

#define MMA16816(d, a, b0, b1) \
    asm volatile("mma.sync.aligned.m16n8k16.row.col.f32.f16.f16.f32 " \
        "{%0,%1,%2,%3}, {%4,%5,%6,%7}, {%8,%9}, {%0,%1,%2,%3};" \
        : "+f"((d)[0]), "+f"((d)[1]), "+f"((d)[2]), "+f"((d)[3]) \
        : "r"((a)[0]), "r"((a)[1]), "r"((a)[2]), "r"((a)[3]), "r"(b0), "r"(b1))

#define SWZ(row, chunk) ((uint32_t)((row) * 128 + (((chunk) ^ ((row) & 7)) << 4)))

// fast softplus: log(1+exp(z)) = max(z,0) + log1p(exp(-|z|)); MUFU-based.
__device__ __forceinline__ float softplus_fast(float z) {
    float t = __expf(-fabsf(z));
    return fmaxf(z, 0.0f) + __logf(1.0f + t);
}

// ---------------- kernel 1: FUSED gating + x-split + W transpose/cast ----------
// gating: 2 tokens/warp, single pass over x, PACKED w in smem (g/n interleaved),
// block-aggregated routing.
#define TOK_PER_WARP 2
#define GATE_BLKS (B_TOK / (8 * TOK_PER_WARP))   // 512

__device__ void gating_block(const float* __restrict__ x,
                             const float* __restrict__ noise,
                             const float* __restrict__ w_gate,
                             const float* __restrict__ w_noise,
                             float* __restrict__ wsm,   // [8][512][4]: {g[d],g[d+1],n[d],n[d+1]}
                             int bx) {
    __shared__ int cnt_s[E_NUM];
    __shared__ int base_s[E_NUM];
    __shared__ int buf_s[E_NUM][16];   // slot ids (b*2+k); <=16 tokens/block per expert

    const int tid  = threadIdx.x;
    const int warp = tid >> 5;
    const int lane = tid & 31;
    const int t0 = (bx * 8 + warp) * TOK_PER_WARP;

    // ---- stage w into packed smem: ws[j][d>>1] = {g[d],g[d+1],n[d],n[d+1]} ----
    const float4* wg4 = (const float4*)w_gate;
    const float4* wn4 = (const float4*)w_noise;
    for (int f = tid; f < 2048; f += 256) {
        float4 g = wg4[f], n = wn4[f];
        int d  = f >> 1;
        int h  = (f & 1) << 2;     // j base: 0 or 4
        int d2 = d >> 1;
        int par = d & 1;           // position within the packed pair
        float gv[4] = {g.x, g.y, g.z, g.w};
        float nv[4] = {n.x, n.y, n.z, n.w};
        #pragma unroll
        for (int q = 0; q < 4; q++) {
            float* base = wsm + (h + q) * 2048 + d2 * 4;
            base[par]     = gv[q];
            base[2 + par] = nv[q];
        }
    }
    if (tid < E_NUM) cnt_s[tid] = 0;
    __syncthreads();

    // ---- single pass: convert x -> fp16 AND accumulate per-lane partial logits ----
    float accG[TOK_PER_WARP][8], accN[TOK_PER_WARP][8];
    #pragma unroll
    for (int t = 0; t < TOK_PER_WARP; t++)
        #pragma unroll
        for (int j = 0; j < 8; j++) { accG[t][j] = 0.f; accN[t][j] = 0.f; }

    #pragma unroll 4
    for (int i = 0; i < 16; i++) {
        int d = 2 * lane + 64 * i;           // even; d>>1 = lane + 32*i
        float2 xv[TOK_PER_WARP];
        #pragma unroll
        for (int t = 0; t < TOK_PER_WARP; t++) {
            xv[t] = *(const float2*)(x + (size_t)(t0 + t) * D_DIM + d);
            ((__half2*)(g_xhi + (size_t)(t0 + t) * D_DIM))[d >> 1] =
                __halves2half2(__float2half_rn(xv[t].x), __float2half_rn(xv[t].y));
        }
        #pragma unroll
        for (int j = 0; j < 8; j++) {
            float4 w4 = *(const float4*)(wsm + j * 2048 + (d >> 1) * 4);
            // w4 = {g[d], g[d+1], n[d], n[d+1]}
            #pragma unroll
            for (int t = 0; t < TOK_PER_WARP; t++) {
                accG[t][j] = fmaf(xv[t].x, w4.x, fmaf(xv[t].y, w4.y, accG[t][j]));
                accN[t][j] = fmaf(xv[t].x, w4.z, fmaf(xv[t].y, w4.w, accN[t][j]));
            }
        }
    }

    // ---- warp reduction (all lanes hold disjoint d-partials) ----
    #pragma unroll
    for (int t = 0; t < TOK_PER_WARP; t++)
        #pragma unroll
        for (int j = 0; j < 8; j++) {
            #pragma unroll
            for (int off = 16; off > 0; off >>= 1) {
                accG[t][j] += __shfl_xor_sync(0xffffffffu, accG[t][j], off);
                accN[t][j] += __shfl_xor_sync(0xffffffffu, accN[t][j], off);
            }
        }

    // ---- routing (lane 0), block-local smem buckets ----
    if (lane == 0) {
        #pragma unroll
        for (int t = 0; t < TOK_PER_WARP; t++) {
            const int b = t0 + t;
            float logits[8];
            #pragma unroll
            for (int j = 0; j < 8; j++) {
                float sd = softplus_fast(accN[t][j]) + 0.01f;
                logits[j] = fmaf(noise[(size_t)b * E_NUM + j], sd, accG[t][j]);
            }
            int i0 = 0; float v0 = logits[0];
            #pragma unroll
            for (int e = 1; e < 8; e++) { if (logits[e] > v0) { v0 = logits[e]; i0 = e; } }
            int i1 = -1; float v1 = -INFINITY;
            #pragma unroll
            for (int e = 0; e < 8; e++) {
                if (e != i0 && logits[e] > v1) { v1 = logits[e]; i1 = e; }
            }
            float ex = __expf(v1 - v0);
            float inv = 1.0f / (1.0f + ex);
            g_gate[b * 2 + 0] = inv;
            g_gate[b * 2 + 1] = ex * inv;

            int p0 = atomicAdd(&cnt_s[i0], 1);
            buf_s[i0][p0] = b * 2 + 0;
            int p1 = atomicAdd(&cnt_s[i1], 1);
            buf_s[i1][p1] = b * 2 + 1;
        }
    }
    __syncthreads();

    // ---- flush: one global atomic per expert per block ----
    if (tid < E_NUM) base_s[tid] = atomicAdd(&g_counts[tid], cnt_s[tid]);
    __syncthreads();
    if (tid < E_NUM * 16) {
        int e = tid >> 4, i = tid & 15;
        if (i < cnt_s[e]) {
            int slot = buf_s[e][i];
            int pos = e * B_TOK + base_s[e] + i;
            g_bucket_tok [pos] = slot >> 1;
            g_bucket_slot[pos] = slot;
        }
    }
}

// prep_w: 64k x 32n tiles, float4 W reads, half2 output stores
__device__ void prep_w_block(const float* __restrict__ W, int t) {
    __shared__ float tile[64][33];
    const int e   = t >> 9;            // 512 tiles per expert
    const int rem = t & 511;
    const int k0  = (rem >> 5) << 6;
    const int n0  = (rem & 31) << 5;
    const int tid = threadIdx.x;
    const float* We = W + (size_t)e * D_DIM * D_DIM;

    #pragma unroll
    for (int i = 0; i < 2; i++) {
        int idx = i * 256 + tid;           // 512 float4 per tile
        int r  = idx >> 3;                 // k-row 0..63
        int c4 = idx & 7;                  // float4 within 32 n
        float4 v = *(const float4*)(We + (size_t)(k0 + r) * D_DIM + n0 + c4 * 4);
        tile[r][c4 * 4 + 0] = v.x;
        tile[r][c4 * 4 + 1] = v.y;
        tile[r][c4 * 4 + 2] = v.z;
        tile[r][c4 * 4 + 3] = v.w;
    }
    __syncthreads();

    #pragma unroll
    for (int j = 0; j < 4; j++) {
        int n  = j * 8 + (tid >> 5);
        int k2 = tid & 31;
        __half2 h2 = __halves2half2(__float2half_rn(tile[2 * k2][n]),
                                    __float2half_rn(tile[2 * k2 + 1][n]));
        __half2* dst = (__half2*)(g_whi + ((size_t)(e * D_DIM + n0 + n)) * D_DIM + k0);
        dst[k2] = h2;
    }
}

__global__ __launch_bounds__(256)
void prep_fused_kernel(const float* __restrict__ x,
                       const float* __restrict__ noise,
                       const float* __restrict__ w_gate,
                       const float* __restrict__ w_noise,
                       const float* __restrict__ W) {
    extern __shared__ float wsm[];
    const int bx = blockIdx.x;
    if (bx < GATE_BLKS) gating_block(x, noise, w_gate, w_noise, wsm, bx);
    else                prep_w_block(W, bx - GATE_BLKS);
}

#define SMEM_PREP 65536   // [8][512][4] floats

// ---------------- kernel 2: routed 1-pass fp16 GEMM (128x128, 2 CTAs/SM) ------
#define BMh 128
#define BNh 128
#define BKh 64
#define NCHUNK (D_DIM / BKh)           // 16
#define STG 32768                      // A 16K | B 16K
#define OFF_B 16384
#define NSTAGE 3
#define NTHR 256
#define SMEM_GEMM (1024 + NSTAGE * STG)

__device__ __forceinline__ void load_stage(uint32_t sbuf, const int* stok,
                                           const __half* __restrict__ wh,
                                           int kt, int tid) {
    #pragma unroll
    for (int i = 0; i < 4; i++) {              // A: 128 rows x 8 chunks
        int lin = i * NTHR + tid;
        int row = lin >> 3, ch = lin & 7;
        int tok = stok[row];
        const __half* sa = g_xhi + (size_t)tok * D_DIM + kt + ch * 8;
        CP16(sbuf + SWZ(row, ch), sa);
    }
    #pragma unroll
    for (int i = 0; i < 4; i++) {              // B: 128 rows x 8 chunks
        int lin = i * NTHR + tid;
        int row = lin >> 3, ch = lin & 7;
        const __half* sb = wh + (size_t)row * D_DIM + kt + ch * 8;
        CP16(sbuf + OFF_B + SWZ(row, ch), sb);
    }
}

__global__ __launch_bounds__(NTHR, 2)
void expert_hmma_kernel(const float* __restrict__ bias) {
    const int e     = blockIdx.z;
    const int count = g_counts[e];
    const int m0    = blockIdx.y * BMh;
    if (m0 >= count) return;
    const int n0    = blockIdx.x * BNh;

    extern __shared__ char smraw[];
    int* stok  = (int*)smraw;            // [128]
    int* sslot = (int*)(smraw + 512);    // [128]
    const uint32_t sbase = smem_u32(smraw) + 1024;
    uint32_t sbuf3[NSTAGE];
    #pragma unroll
    for (int s = 0; s < NSTAGE; s++) sbuf3[s] = sbase + s * STG;

    const int tid  = threadIdx.x;
    const int wid  = tid >> 5;
    const int lane = tid & 31;
    const int wm   = (wid & 3) * 32;     // 4 warps over 128 m
    const int wn   = (wid >> 2) * 64;    // 2 warps over 128 n

    if (tid < BMh) {
        int m = m0 + tid;
        bool ok = (m < count);
        stok [tid] = ok ? g_bucket_tok [e * B_TOK + m] : 0;
        sslot[tid] = ok ? g_bucket_slot[e * B_TOK + m] : -1;
    }
    __syncthreads();

    const __half* wh = g_whi + ((size_t)e * D_DIM + n0) * D_DIM;

    float acc[2][8][4];
    #pragma unroll
    for (int mt = 0; mt < 2; mt++)
        #pragma unroll
        for (int nt = 0; nt < 8; nt++)
            #pragma unroll
            for (int c = 0; c < 4; c++) acc[mt][nt][c] = 0.0f;

    load_stage(sbuf3[0], stok, wh, 0, tid);
    CP_COMMIT();
    load_stage(sbuf3[1], stok, wh, BKh, tid);
    CP_COMMIT();

    const int lrow = lane & 15;
    const int lsel = lane >> 4;

    int sidx = 0;
    int pidx = 2;
    for (int c = 0; c < NCHUNK; c++) {
        if (c == NCHUNK - 1) { CP_WAIT0(); } else { CP_WAIT1(); }
        __syncthreads();
        if (c + 2 < NCHUNK) {
            load_stage(sbuf3[pidx], stok, wh, (c + 2) * BKh, tid);
            CP_COMMIT();
        }

        const uint32_t sbuf = sbuf3[sidx];
        #pragma unroll
        for (int ks = 0; ks < 4; ks++) {
            const int chunk = ks * 2 + lsel;
            uint32_t ahi[2][4];
            #pragma unroll
            for (int mt = 0; mt < 2; mt++) {
                int r = wm + mt * 16 + lrow;
                LDSM4(ahi[mt], sbuf + SWZ(r, chunk));
            }
            #pragma unroll
            for (int ng = 0; ng < 4; ng++) {
                int r = wn + ng * 16 + lrow;
                uint32_t bhi[4];
                LDSM4(bhi, sbuf + OFF_B + SWZ(r, chunk));
                #pragma unroll
                for (int mt = 0; mt < 2; mt++) {
                    #pragma unroll
                    for (int o = 0; o < 2; o++)
                        MMA16816(acc[mt][ng * 2 + o], ahi[mt], bhi[o], bhi[2 + o]);
                }
            }
        }

        sidx = (sidx + 1 == NSTAGE) ? 0 : sidx + 1;
        pidx = (pidx + 1 == NSTAGE) ? 0 : pidx + 1;
    }

    // epilogue: fused bias + fast exp, scatter to per-slot partials
    #pragma unroll
    for (int mt = 0; mt < 2; mt++) {
        #pragma unroll
        for (int h = 0; h < 2; h++) {
            int m = wm + mt * 16 + (lane >> 2) + h * 8;
            int slot = sslot[m];
            if (slot < 0) continue;
            float* pr = g_partial + ((size_t)slot << 10);
            #pragma unroll
            for (int nt = 0; nt < 8; nt++) {
                int col = n0 + wn + nt * 8 + (lane & 3) * 2;
                float2 bv = *(const float2*)(bias + (size_t)e * D_DIM + col);
                float2 o;
                o.x = __expf(acc[mt][nt][h * 2 + 0] + bv.x);
                o.y = __expf(acc[mt][nt][h * 2 + 1] + bv.y);
                *(float2*)(pr + col) = o;
            }
        }
    }
}

// ---------------- kernel 3: combine (8 elems/thread, fast log) -----------------
__device__ __forceinline__ float safelog(float c) {
    const float EPSF = 2.2204460492503131e-16f;
    return __logf(c == 0.0f ? EPSF : c);
}

__global__ void combine_kernel(float* __restrict__ out) {
    int idx = blockIdx.x * 256 + threadIdx.x;        // over B*D/8
    int b  = idx >> 7;
    int h8 = (idx & 127) << 3;
    float g0 = g_gate[b * 2 + 0];
    float g1 = g_gate[b * 2 + 1];
    const float* p0p = g_partial + ((size_t)(b * 2 + 0) << 10) + h8;
    const float* p1p = g_partial + ((size_t)(b * 2 + 1) << 10) + h8;
    float4 p0a = *(const float4*)(p0p);
    float4 p0b = *(const float4*)(p0p + 4);
    float4 p1a = *(const float4*)(p1p);
    float4 p1b = *(const float4*)(p1p + 4);
    float4 oa, ob;
    oa.x = safelog(fmaf(g0, p0a.x, g1 * p1a.x));
    oa.y = safelog(fmaf(g0, p0a.y, g1 * p1a.y));
    oa.z = safelog(fmaf(g0, p0a.z, g1 * p1a.z));
    oa.w = safelog(fmaf(g0, p0a.w, g1 * p1a.w));
    ob.x = safelog(fmaf(g0, p0b.x, g1 * p1b.x));
    ob.y = safelog(fmaf(g0, p0b.y, g1 * p1b.y));
    ob.z = safelog(fmaf(g0, p0b.z, g1 * p1b.z));
    ob.w = safelog(fmaf(g0, p0b.w, g1 * p1b.w));
    float* op = out + (size_t)b * D_DIM + h8;
    *(float4*)(op)     = oa;
    *(float4*)(op + 4) = ob;

    // reset bucket counts for the next kernel_launch call
    if (blockIdx.x == 0 && threadIdx.x < E_NUM) g_counts[threadIdx.x] = 0;
}

// ---------------- launch ----------------
extern "C" void kernel_launch(void* const* d_in, const int* in_sizes, int n_in,
                              void* d_out, int out_size) {
    const float* x         = (const float*)d_in[0];
    const float* noise     = (const float*)d_in[1];
    const float* w_gate    = (const float*)d_in[2];
    const float* w_noise   = (const float*)d_in[3];
    const float* W_experts = (const float*)d_in[4];
    const float* b_experts = (const float*)d_in[5];
    float* out = (float*)d_out;

    cudaFuncSetAttribute(prep_fused_kernel,
                         cudaFuncAttributeMaxDynamicSharedMemorySize, SMEM_PREP);
    cudaFuncSetAttribute(expert_hmma_kernel,
                         cudaFuncAttributeMaxDynamicSharedMemorySize, SMEM_GEMM);

    prep_fused_kernel<<<GATE_BLKS + 4096, 256, SMEM_PREP>>>(x, noise, w_gate, w_noise, W_experts);

    dim3 ggrid(D_DIM / BNh, B_TOK / BMh, E_NUM);  // (8, 64, 8)
    expert_hmma_kernel<<<ggrid, NTHR, SMEM_GEMM>>>(b_experts);

    combine_kernel<<<(B_TOK * D_DIM / 8) / 256, 256>>>(out);
}